// round 13
// baseline (speedup 1.0000x reference)
#include <cuda_runtime.h>

#define B_    8192
#define K_    6
#define T_    30
#define GH    256
#define BK    (B_ * K_)     // 49152
#define ROWS  64
#define NCTA  (BK / ROWS)   // 768
#define NTHR  512           // 16 warps, 4 rows per warp
#define RPW   4             // rows per warp

// ---------------- SMEM layout (float offsets) ----------------
#define SM_FLOATS 40452

// Pre-transposed weights (k-major, k-pairs packed as float2 for FFMA2)
__device__ float2 g_Wh0t[146 * 256];  // [k2][i], k padded 290->292
__device__ float2 g_Wp[128 * 768];    // [k2][g], W_hh

__global__ void prep_kernel(const float* __restrict__ Wh0,
                            const float* __restrict__ Whh) {
    int idx = blockIdx.x * blockDim.x + threadIdx.x;
    if (idx < 146 * 256) {
        int k2 = idx / 256, i = idx % 256;
        int k0 = 2 * k2;
        float f0 = (k0     < 290) ? Wh0[i * 290 + k0]     : 0.0f;
        float f1 = (k0 + 1 < 290) ? Wh0[i * 290 + k0 + 1] : 0.0f;
        g_Wh0t[idx] = make_float2(f0, f1);
    }
    int idx2 = idx - 146 * 256;
    if (idx2 >= 0 && idx2 < 128 * 768) {
        int k2 = idx2 / 768, g = idx2 % 768;
        g_Wp[idx2] = make_float2(Whh[g * 256 + 2 * k2],
                                 Whh[g * 256 + 2 * k2 + 1]);
    }
}

// Packed fp32x2 FMA (B300 FFMA2) — only reachable via PTX.
__device__ __forceinline__ void ffma2(unsigned long long& c,
                                      unsigned long long a,
                                      unsigned long long b) {
    asm("fma.rn.f32x2 %0, %1, %2, %0;" : "+l"(c) : "l"(a), "l"(b));
}
__device__ __forceinline__ float fsum2(unsigned long long v) {
    float lo, hi;
    asm("mov.b64 {%0,%1}, %2;" : "=f"(lo), "=f"(hi) : "l"(v));
    return lo + hi;
}
__device__ __forceinline__ float sigm(float x) {
    return __fdividef(1.0f, 1.0f + __expf(-x));
}
__device__ __forceinline__ float tanhfast(float x) {
    float ax = fabsf(x);
    float e = __expf(-2.0f * ax);
    float t = __fdividef(1.0f - e, 1.0f + e);
    return copysignf(t, x);
}

extern "C" __global__ void __launch_bounds__(NTHR, 1)
traj_kernel(const float* __restrict__ context, const float* __restrict__ goals,
            const float* __restrict__ intent,  const float* __restrict__ b_h0,
            const float* __restrict__ W_ih,    const float* __restrict__ b_ih,
            const float* __restrict__ b_hh,    const float* __restrict__ W_out,
            const float* __restrict__ b_out,   float* __restrict__ out) {
    extern __shared__ float sm[];
    const int tid  = threadIdx.x;
    const int lane = tid & 31;
    const int warp = tid >> 5;
    const int r0   = warp * RPW;        // warp-private row block (4 rows)
    const int row0 = blockIdx.x * ROWS;

    float* HA    = sm;
    float* HB    = sm + 16384;
    float* PRED  = sm + 32768;
    float* WIHs  = sm + 36608;
    float* BIHs  = sm + 38144;
    float* BHHs  = sm + 38912;
    float* WOUTs = sm + 39680;
    float* BOUTs = sm + 40192;
    float* GOALS = sm + 40196;
    float* POSs  = sm + 40324;
    float* X     = sm + 16384;          // overlay on HB..PRED (dead during init)

    // ---- stage X = [context | goal | intent | pad] : 64 x 292 ----
    for (int idx = tid; idx < ROWS * 292; idx += NTHR) {
        int r = idx / 292, c = idx % 292;
        int row = row0 + r, b = row / K_;
        float v;
        if (c < 256)      v = context[b * 256 + c];
        else if (c < 258) v = goals[row * 2 + (c - 256)];
        else if (c < 290) v = intent[b * 32 + (c - 258)];
        else              v = 0.0f;
        X[idx] = v;
    }
    __syncthreads();

    // ---- init GEMM: h0 = X @ W_h0^T + b_h0  (K=292 padded) ----
    {
        const unsigned long long* W0 =
            reinterpret_cast<const unsigned long long*>(g_Wh0t);
        for (int it = 0; it < 8; it++) {
            int i = it * 32 + lane;
            unsigned long long acc[RPW];
            #pragma unroll
            for (int rr = 0; rr < RPW; rr++) acc[rr] = 0ull;
            #pragma unroll 4
            for (int kk = 0; kk < 73; kk++) {
                unsigned long long w0 = W0[(2 * kk)     * 256 + i];
                unsigned long long w1 = W0[(2 * kk + 1) * 256 + i];
                #pragma unroll
                for (int rr = 0; rr < RPW; rr++) {
                    ulonglong2 hv = *reinterpret_cast<const ulonglong2*>(
                        X + (r0 + rr) * 292 + kk * 4);
                    ffma2(acc[rr], hv.x, w0);
                    ffma2(acc[rr], hv.y, w1);
                }
            }
            float bb = b_h0[i];
            #pragma unroll
            for (int rr = 0; rr < RPW; rr++)
                HA[(r0 + rr) * 256 + i] = fsum2(acc[rr]) + bb;
        }
    }
    __syncthreads();   // X is dead after this point

    // ---- load constants into SMEM ----
    for (int idx = tid; idx < 1536; idx += NTHR) WIHs[idx] = W_ih[idx];
    for (int idx = tid; idx < 768;  idx += NTHR) { BIHs[idx] = b_ih[idx]; BHHs[idx] = b_hh[idx]; }
    for (int idx = tid; idx < 512;  idx += NTHR) WOUTs[idx] = W_out[idx];
    if (tid < 2) BOUTs[tid] = b_out[tid];
    for (int idx = tid; idx < 128;  idx += NTHR) { GOALS[idx] = goals[row0 * 2 + idx]; POSs[idx] = 0.0f; }
    __syncthreads();

    // ---- T-step GRU recurrence: fully warp-private (no block syncs) ----
    const unsigned long long* WP =
        reinterpret_cast<const unsigned long long*>(g_Wp);
    float* hc  = HA;
    float* hnx = HB;
    for (int t = 0; t < T_; t++) {
        float p0[RPW], p1[RPW];
        #pragma unroll
        for (int rr = 0; rr < RPW; rr++) {
            p0[rr] = POSs[(r0 + rr) * 2 + 0];
            p1[rr] = POSs[(r0 + rr) * 2 + 1];
        }
        float dAcc[2 * RPW];
        #pragma unroll
        for (int i = 0; i < 2 * RPW; i++) dAcc[i] = 0.0f;

        for (int jt = 0; jt < 8; jt++) {
            const int jj = jt * 32 + lane;
            unsigned long long ar2[RPW], az2[RPW], an2[RPW];
            #pragma unroll
            for (int rr = 0; rr < RPW; rr++) { ar2[rr] = 0ull; az2[rr] = 0ull; an2[rr] = 0ull; }

            #pragma unroll 2
            for (int kk = 0; kk < 64; kk++) {
                // lane-coalesced k-major weight pairs (LDG.64, L1-hit after first warp)
                unsigned long long wr0 = WP[(2 * kk)     * 768 +       jj];
                unsigned long long wz0 = WP[(2 * kk)     * 768 + 256 + jj];
                unsigned long long wn0 = WP[(2 * kk)     * 768 + 512 + jj];
                unsigned long long wr1 = WP[(2 * kk + 1) * 768 +       jj];
                unsigned long long wz1 = WP[(2 * kk + 1) * 768 + 256 + jj];
                unsigned long long wn1 = WP[(2 * kk + 1) * 768 + 512 + jj];
                #pragma unroll
                for (int rr = 0; rr < RPW; rr++) {
                    ulonglong2 hv = *reinterpret_cast<const ulonglong2*>(
                        hc + (r0 + rr) * 256 + kk * 4);  // broadcast LDS.128
                    ffma2(ar2[rr], hv.x, wr0); ffma2(ar2[rr], hv.y, wr1);
                    ffma2(az2[rr], hv.x, wz0); ffma2(az2[rr], hv.y, wz1);
                    ffma2(an2[rr], hv.x, wn0); ffma2(an2[rr], hv.y, wn1);
                }
            }

            // gate math for this j-column, 4 rows
            float wir0 = WIHs[jj * 2],          wir1 = WIHs[jj * 2 + 1];
            float wiz0 = WIHs[(jj + 256) * 2],  wiz1 = WIHs[(jj + 256) * 2 + 1];
            float win0 = WIHs[(jj + 512) * 2],  win1 = WIHs[(jj + 512) * 2 + 1];
            float bir  = BIHs[jj], biz = BIHs[jj + 256], bin = BIHs[jj + 512];
            float bhr  = BHHs[jj], bhz = BHHs[jj + 256], bhn = BHHs[jj + 512];
            float wo0  = WOUTs[jj], wo1 = WOUTs[256 + jj];
            #pragma unroll
            for (int rr = 0; rr < RPW; rr++) {
                int r = r0 + rr;
                float ghr = fsum2(ar2[rr]) + bhr;
                float ghz = fsum2(az2[rr]) + bhz;
                float ghn = fsum2(an2[rr]) + bhn;
                float gir = fmaf(p0[rr], wir0, fmaf(p1[rr], wir1, bir));
                float giz = fmaf(p0[rr], wiz0, fmaf(p1[rr], wiz1, biz));
                float gin = fmaf(p0[rr], win0, fmaf(p1[rr], win1, bin));
                float rg  = sigm(gir + ghr);
                float zg  = sigm(giz + ghz);
                float ng  = tanhfast(fmaf(rg, ghn, gin));
                float hold = hc[r * 256 + jj];
                float hnew = fmaf(zg, hold - ng, ng);   // (1-z)n + z h
                hnx[r * 256 + jj] = hnew;
                dAcc[rr * 2 + 0] = fmaf(hnew, wo0, dAcc[rr * 2 + 0]);
                dAcc[rr * 2 + 1] = fmaf(hnew, wo1, dAcc[rr * 2 + 1]);
            }
        }

        // warp butterfly reduce delta over the 256 hidden units
        #pragma unroll
        for (int i = 0; i < 2 * RPW; i++) {
            #pragma unroll
            for (int off = 16; off; off >>= 1)
                dAcc[i] += __shfl_xor_sync(0xffffffffu, dAcc[i], off);
        }
        if (lane < 2 * RPW) {
            int rr = lane >> 1, d = lane & 1;
            float np = POSs[(r0 + rr) * 2 + d] + dAcc[lane] + BOUTs[d];
            POSs[(r0 + rr) * 2 + d] = np;
            PRED[(r0 + rr) * 60 + t * 2 + d] = np;
        }
        __syncwarp();
        float* tmp = hc; hc = hnx; hnx = tmp;
    }
    __syncthreads();

    // ---- goal-anchored correction + output write (B,K,T,2) ----
    const float inv = 1.0f / 30.0f;
    for (int idx = tid; idx < ROWS * 60; idx += NTHR) {
        int r = idx / 60, rem = idx % 60;
        int tt = rem >> 1, d = rem & 1;
        float last = PRED[r * 60 + 58 + d];
        float corr = GOALS[r * 2 + d] - last;
        out[(row0 + r) * 60 + rem] = PRED[idx] + corr * (float)(tt + 1) * inv;
    }
}

extern "C" void kernel_launch(void* const* d_in, const int* in_sizes, int n_in,
                              void* d_out, int out_size) {
    const float* context = (const float*)d_in[0];
    const float* goals   = (const float*)d_in[1];
    const float* intent  = (const float*)d_in[2];
    const float* W_h0    = (const float*)d_in[3];
    const float* b_h0    = (const float*)d_in[4];
    const float* W_ih    = (const float*)d_in[5];
    const float* W_hh    = (const float*)d_in[6];
    const float* b_ih    = (const float*)d_in[7];
    const float* b_hh    = (const float*)d_in[8];
    const float* W_out   = (const float*)d_in[9];
    const float* b_out   = (const float*)d_in[10];
    float* out = (float*)d_out;

    int prep_n = 146 * 256 + 128 * 768;
    prep_kernel<<<(prep_n + 255) / 256, 256>>>(W_h0, W_hh);

    size_t smem = SM_FLOATS * sizeof(float);
    cudaFuncSetAttribute(traj_kernel,
                         cudaFuncAttributeMaxDynamicSharedMemorySize, (int)smem);
    traj_kernel<<<NCTA, NTHR, smem>>>(context, goals, intent, b_h0,
                                      W_ih, b_ih, b_hh, W_out, b_out, out);
}

// round 14
// speedup vs baseline: 1.3444x; 1.3444x over previous
#include <cuda_runtime.h>

#define B_    8192
#define K_    6
#define T_    30
#define GH    256
#define BK    (B_ * K_)     // 49152
#define ROWS  64
#define NCTA  (BK / ROWS)   // 768
#define NTHR  512           // 16 warps, 4 rows per warp
#define RPW   4             // rows per warp

// ---------------- SMEM layout (float offsets) ----------------
#define SM_FLOATS 40452

// Pre-transposed weights (k-major, k-pairs packed as float2 for FFMA2)
__device__ float2 g_Wh0t[146 * 256];  // [k2][i], k padded 290->292
__device__ float2 g_Wp[128 * 768];    // [k2][g], W_hh

__global__ void prep_kernel(const float* __restrict__ Wh0,
                            const float* __restrict__ Whh) {
    int idx = blockIdx.x * blockDim.x + threadIdx.x;
    if (idx < 146 * 256) {
        int k2 = idx / 256, i = idx % 256;
        int k0 = 2 * k2;
        float f0 = (k0     < 290) ? Wh0[i * 290 + k0]     : 0.0f;
        float f1 = (k0 + 1 < 290) ? Wh0[i * 290 + k0 + 1] : 0.0f;
        g_Wh0t[idx] = make_float2(f0, f1);
    }
    int idx2 = idx - 146 * 256;
    if (idx2 >= 0 && idx2 < 128 * 768) {
        int k2 = idx2 / 768, g = idx2 % 768;
        g_Wp[idx2] = make_float2(Whh[g * 256 + 2 * k2],
                                 Whh[g * 256 + 2 * k2 + 1]);
    }
}

// Packed fp32x2 FMA (B300 FFMA2) — only reachable via PTX.
__device__ __forceinline__ void ffma2(unsigned long long& c,
                                      unsigned long long a,
                                      unsigned long long b) {
    asm("fma.rn.f32x2 %0, %1, %2, %0;" : "+l"(c) : "l"(a), "l"(b));
}
__device__ __forceinline__ float fsum2(unsigned long long v) {
    float lo, hi;
    asm("mov.b64 {%0,%1}, %2;" : "=f"(lo), "=f"(hi) : "l"(v));
    return lo + hi;
}
__device__ __forceinline__ float sigm(float x) {
    return __fdividef(1.0f, 1.0f + __expf(-x));
}
__device__ __forceinline__ float tanhfast(float x) {
    float ax = fabsf(x);
    float e = __expf(-2.0f * ax);
    float t = __fdividef(1.0f - e, 1.0f + e);
    return copysignf(t, x);
}

extern "C" __global__ void __launch_bounds__(NTHR, 1)
traj_kernel(const float* __restrict__ context, const float* __restrict__ goals,
            const float* __restrict__ intent,  const float* __restrict__ b_h0,
            const float* __restrict__ W_ih,    const float* __restrict__ b_ih,
            const float* __restrict__ b_hh,    const float* __restrict__ W_out,
            const float* __restrict__ b_out,   float* __restrict__ out) {
    extern __shared__ float sm[];
    const int tid  = threadIdx.x;
    const int lane = tid & 31;
    const int warp = tid >> 5;
    const int r0   = warp * RPW;        // warp-private row block (4 rows)
    const int row0 = blockIdx.x * ROWS;

    float* HA    = sm;
    float* HB    = sm + 16384;
    float* PRED  = sm + 32768;
    float* WIHs  = sm + 36608;
    float* BIHs  = sm + 38144;
    float* BHHs  = sm + 38912;
    float* WOUTs = sm + 39680;
    float* BOUTs = sm + 40192;
    float* GOALS = sm + 40196;
    float* POSs  = sm + 40324;
    float* X     = sm + 16384;          // overlay on HB..PRED (dead during init)

    // ---- stage X = [context | goal | intent | pad] : 64 x 292 ----
    for (int idx = tid; idx < ROWS * 292; idx += NTHR) {
        int r = idx / 292, c = idx % 292;
        int row = row0 + r, b = row / K_;
        float v;
        if (c < 256)      v = context[b * 256 + c];
        else if (c < 258) v = goals[row * 2 + (c - 256)];
        else if (c < 290) v = intent[b * 32 + (c - 258)];
        else              v = 0.0f;
        X[idx] = v;
    }
    __syncthreads();

    // ---- init GEMM: h0 = X @ W_h0^T + b_h0  (K=292 padded) ----
    {
        const unsigned long long* W0 =
            reinterpret_cast<const unsigned long long*>(g_Wh0t);
        for (int it = 0; it < 8; it++) {
            int i = it * 32 + lane;
            unsigned long long acc[RPW];
            #pragma unroll
            for (int rr = 0; rr < RPW; rr++) acc[rr] = 0ull;
            #pragma unroll 4
            for (int kk = 0; kk < 73; kk++) {
                unsigned long long w0 = W0[(2 * kk)     * 256 + i];
                unsigned long long w1 = W0[(2 * kk + 1) * 256 + i];
                #pragma unroll
                for (int rr = 0; rr < RPW; rr++) {
                    ulonglong2 hv = *reinterpret_cast<const ulonglong2*>(
                        X + (r0 + rr) * 292 + kk * 4);
                    ffma2(acc[rr], hv.x, w0);
                    ffma2(acc[rr], hv.y, w1);
                }
            }
            float bb = b_h0[i];
            #pragma unroll
            for (int rr = 0; rr < RPW; rr++)
                HA[(r0 + rr) * 256 + i] = fsum2(acc[rr]) + bb;
        }
    }
    __syncthreads();   // X is dead after this point

    // ---- load constants into SMEM ----
    for (int idx = tid; idx < 1536; idx += NTHR) WIHs[idx] = W_ih[idx];
    for (int idx = tid; idx < 768;  idx += NTHR) { BIHs[idx] = b_ih[idx]; BHHs[idx] = b_hh[idx]; }
    for (int idx = tid; idx < 512;  idx += NTHR) WOUTs[idx] = W_out[idx];
    if (tid < 2) BOUTs[tid] = b_out[tid];
    for (int idx = tid; idx < 128;  idx += NTHR) { GOALS[idx] = goals[row0 * 2 + idx]; POSs[idx] = 0.0f; }
    __syncthreads();

    // ---- T-step GRU recurrence: fully warp-private (no block syncs) ----
    const unsigned long long* WP =
        reinterpret_cast<const unsigned long long*>(g_Wp);
    float* hc  = HA;
    float* hnx = HB;
    for (int t = 0; t < T_; t++) {
        float p0[RPW], p1[RPW];
        #pragma unroll
        for (int rr = 0; rr < RPW; rr++) {
            p0[rr] = POSs[(r0 + rr) * 2 + 0];
            p1[rr] = POSs[(r0 + rr) * 2 + 1];
        }
        float dAcc[2 * RPW];
        #pragma unroll
        for (int i = 0; i < 2 * RPW; i++) dAcc[i] = 0.0f;

        for (int jt = 0; jt < 8; jt++) {
            const int jj = jt * 32 + lane;
            unsigned long long ar2[RPW], az2[RPW], an2[RPW];
            #pragma unroll
            for (int rr = 0; rr < RPW; rr++) { ar2[rr] = 0ull; az2[rr] = 0ull; an2[rr] = 0ull; }

            #pragma unroll 2
            for (int kk = 0; kk < 64; kk++) {
                // lane-coalesced k-major weight pairs (LDG.64, L1-hit after first warp)
                unsigned long long wr0 = WP[(2 * kk)     * 768 +       jj];
                unsigned long long wz0 = WP[(2 * kk)     * 768 + 256 + jj];
                unsigned long long wn0 = WP[(2 * kk)     * 768 + 512 + jj];
                unsigned long long wr1 = WP[(2 * kk + 1) * 768 +       jj];
                unsigned long long wz1 = WP[(2 * kk + 1) * 768 + 256 + jj];
                unsigned long long wn1 = WP[(2 * kk + 1) * 768 + 512 + jj];
                #pragma unroll
                for (int rr = 0; rr < RPW; rr++) {
                    ulonglong2 hv = *reinterpret_cast<const ulonglong2*>(
                        hc + (r0 + rr) * 256 + kk * 4);  // broadcast LDS.128
                    ffma2(ar2[rr], hv.x, wr0); ffma2(ar2[rr], hv.y, wr1);
                    ffma2(az2[rr], hv.x, wz0); ffma2(az2[rr], hv.y, wz1);
                    ffma2(an2[rr], hv.x, wn0); ffma2(an2[rr], hv.y, wn1);
                }
            }

            // gate math for this j-column, 4 rows
            float wir0 = WIHs[jj * 2],          wir1 = WIHs[jj * 2 + 1];
            float wiz0 = WIHs[(jj + 256) * 2],  wiz1 = WIHs[(jj + 256) * 2 + 1];
            float win0 = WIHs[(jj + 512) * 2],  win1 = WIHs[(jj + 512) * 2 + 1];
            float bir  = BIHs[jj], biz = BIHs[jj + 256], bin = BIHs[jj + 512];
            float bhr  = BHHs[jj], bhz = BHHs[jj + 256], bhn = BHHs[jj + 512];
            float wo0  = WOUTs[jj], wo1 = WOUTs[256 + jj];
            #pragma unroll
            for (int rr = 0; rr < RPW; rr++) {
                int r = r0 + rr;
                float ghr = fsum2(ar2[rr]) + bhr;
                float ghz = fsum2(az2[rr]) + bhz;
                float ghn = fsum2(an2[rr]) + bhn;
                float gir = fmaf(p0[rr], wir0, fmaf(p1[rr], wir1, bir));
                float giz = fmaf(p0[rr], wiz0, fmaf(p1[rr], wiz1, biz));
                float gin = fmaf(p0[rr], win0, fmaf(p1[rr], win1, bin));
                float rg  = sigm(gir + ghr);
                float zg  = sigm(giz + ghz);
                float ng  = tanhfast(fmaf(rg, ghn, gin));
                float hold = hc[r * 256 + jj];
                float hnew = fmaf(zg, hold - ng, ng);   // (1-z)n + z h
                hnx[r * 256 + jj] = hnew;
                dAcc[rr * 2 + 0] = fmaf(hnew, wo0, dAcc[rr * 2 + 0]);
                dAcc[rr * 2 + 1] = fmaf(hnew, wo1, dAcc[rr * 2 + 1]);
            }
        }

        // warp butterfly reduce delta over the 256 hidden units
        #pragma unroll
        for (int i = 0; i < 2 * RPW; i++) {
            #pragma unroll
            for (int off = 16; off; off >>= 1)
                dAcc[i] += __shfl_xor_sync(0xffffffffu, dAcc[i], off);
        }
        if (lane < 2 * RPW) {
            int rr = lane >> 1, d = lane & 1;
            float np = POSs[(r0 + rr) * 2 + d] + dAcc[lane] + BOUTs[d];
            POSs[(r0 + rr) * 2 + d] = np;
            PRED[(r0 + rr) * 60 + t * 2 + d] = np;
        }
        __syncwarp();
        float* tmp = hc; hc = hnx; hnx = tmp;
    }
    __syncthreads();

    // ---- goal-anchored correction + output write (B,K,T,2) ----
    const float inv = 1.0f / 30.0f;
    for (int idx = tid; idx < ROWS * 60; idx += NTHR) {
        int r = idx / 60, rem = idx % 60;
        int tt = rem >> 1, d = rem & 1;
        float last = PRED[r * 60 + 58 + d];
        float corr = GOALS[r * 2 + d] - last;
        out[(row0 + r) * 60 + rem] = PRED[idx] + corr * (float)(tt + 1) * inv;
    }
}

extern "C" void kernel_launch(void* const* d_in, const int* in_sizes, int n_in,
                              void* d_out, int out_size) {
    const float* context = (const float*)d_in[0];
    const float* goals   = (const float*)d_in[1];
    const float* intent  = (const float*)d_in[2];
    const float* W_h0    = (const float*)d_in[3];
    const float* b_h0    = (const float*)d_in[4];
    const float* W_ih    = (const float*)d_in[5];
    const float* W_hh    = (const float*)d_in[6];
    const float* b_ih    = (const float*)d_in[7];
    const float* b_hh    = (const float*)d_in[8];
    const float* W_out   = (const float*)d_in[9];
    const float* b_out   = (const float*)d_in[10];
    float* out = (float*)d_out;

    int prep_n = 146 * 256 + 128 * 768;
    prep_kernel<<<(prep_n + 255) / 256, 256>>>(W_h0, W_hh);

    size_t smem = SM_FLOATS * sizeof(float);
    cudaFuncSetAttribute(traj_kernel,
                         cudaFuncAttributeMaxDynamicSharedMemorySize, (int)smem);
    traj_kernel<<<NCTA, NTHR, smem>>>(context, goals, intent, b_h0,
                                      W_ih, b_ih, b_hh, W_out, b_out, out);
}

// round 15
// speedup vs baseline: 1.6474x; 1.2254x over previous
#include <cuda_runtime.h>

#define B_    8192
#define K_    6
#define T_    30
#define GH    256
#define BK    (B_ * K_)     // 49152
#define ROWS  64
#define NCTA  (BK / ROWS)   // 768
#define NTHR  256           // 8 warps
#define RT    16            // rows per pass (j-sliced GEMM)
#define NPASS (ROWS / RT)   // 4

// ---------------- SMEM layout (float offsets) ----------------
#define SM_FLOATS 40452

// Pre-transposed weights (k-major, k-pairs packed as float2 for FFMA2)
__device__ float2 g_Wh0t[146 * 256];  // [k2][i], k padded 290->292
__device__ float2 g_Wp[128 * 768];    // [k2][g], W_hh

__global__ void prep_kernel(const float* __restrict__ Wh0,
                            const float* __restrict__ Whh) {
    int idx = blockIdx.x * blockDim.x + threadIdx.x;
    if (idx < 146 * 256) {
        int k2 = idx / 256, i = idx % 256;
        int k0 = 2 * k2;
        float f0 = (k0     < 290) ? Wh0[i * 290 + k0]     : 0.0f;
        float f1 = (k0 + 1 < 290) ? Wh0[i * 290 + k0 + 1] : 0.0f;
        g_Wh0t[idx] = make_float2(f0, f1);
    }
    int idx2 = idx - 146 * 256;
    if (idx2 >= 0 && idx2 < 128 * 768) {
        int k2 = idx2 / 768, g = idx2 % 768;
        g_Wp[idx2] = make_float2(Whh[g * 256 + 2 * k2],
                                 Whh[g * 256 + 2 * k2 + 1]);
    }
}

// Packed fp32x2 FMA (B300 FFMA2) — only reachable via PTX.
__device__ __forceinline__ void ffma2(unsigned long long& c,
                                      unsigned long long a,
                                      unsigned long long b) {
    asm("fma.rn.f32x2 %0, %1, %2, %0;" : "+l"(c) : "l"(a), "l"(b));
}
__device__ __forceinline__ float fsum2(unsigned long long v) {
    float lo, hi;
    asm("mov.b64 {%0,%1}, %2;" : "=f"(lo), "=f"(hi) : "l"(v));
    return lo + hi;
}
__device__ __forceinline__ float sigm(float x) {
    return __fdividef(1.0f, 1.0f + __expf(-x));
}
__device__ __forceinline__ float tanhfast(float x) {
    float ax = fabsf(x);
    float e = __expf(-2.0f * ax);
    float t = __fdividef(1.0f - e, 1.0f + e);
    return copysignf(t, x);
}

extern "C" __global__ void __launch_bounds__(NTHR, 1)
traj_kernel(const float* __restrict__ context, const float* __restrict__ goals,
            const float* __restrict__ intent,  const float* __restrict__ b_h0,
            const float* __restrict__ W_ih,    const float* __restrict__ b_ih,
            const float* __restrict__ b_hh,    const float* __restrict__ W_out,
            const float* __restrict__ b_out,   float* __restrict__ out) {
    extern __shared__ float sm[];
    const int tid  = threadIdx.x;
    const int lane = tid & 31;
    const int warp = tid >> 5;
    const int row0 = blockIdx.x * ROWS;

    float* HA    = sm;
    float* HB    = sm + 16384;
    float* PRED  = sm + 32768;
    float* WIHs  = sm + 36608;
    float* BIHs  = sm + 38144;
    float* BHHs  = sm + 38912;
    float* WOUTs = sm + 39680;
    float* BOUTs = sm + 40192;
    float* GOALS = sm + 40196;
    float* POSs  = sm + 40324;
    float* X     = sm + 16384;          // overlay on HB..PRED (dead during init)

    // ---- stage X = [context | goal | intent | pad] : 64 x 292 ----
    for (int idx = tid; idx < ROWS * 292; idx += NTHR) {
        int r = idx / 292, c = idx % 292;
        int row = row0 + r, b = row / K_;
        float v;
        if (c < 256)      v = context[b * 256 + c];
        else if (c < 258) v = goals[row * 2 + (c - 256)];
        else if (c < 290) v = intent[b * 32 + (c - 258)];
        else              v = 0.0f;
        X[idx] = v;
    }
    __syncthreads();

    // ---- init GEMM: h0 = X @ W_h0^T + b_h0 (warp-private 8-row blocks) ----
    {
        const int r0i = warp * 8;
        const unsigned long long* W0 =
            reinterpret_cast<const unsigned long long*>(g_Wh0t);
        for (int it = 0; it < 8; it++) {
            int i = it * 32 + lane;
            unsigned long long acc[8];
            #pragma unroll
            for (int rr = 0; rr < 8; rr++) acc[rr] = 0ull;
            #pragma unroll 4
            for (int kk = 0; kk < 73; kk++) {
                unsigned long long w0 = W0[(2 * kk)     * 256 + i];
                unsigned long long w1 = W0[(2 * kk + 1) * 256 + i];
                #pragma unroll
                for (int rr = 0; rr < 8; rr++) {
                    ulonglong2 hv = *reinterpret_cast<const ulonglong2*>(
                        X + (r0i + rr) * 292 + kk * 4);
                    ffma2(acc[rr], hv.x, w0);
                    ffma2(acc[rr], hv.y, w1);
                }
            }
            float bb = b_h0[i];
            #pragma unroll
            for (int rr = 0; rr < 8; rr++)
                HA[(r0i + rr) * 256 + i] = fsum2(acc[rr]) + bb;
        }
    }
    __syncthreads();   // X is dead after this point

    // ---- load constants into SMEM ----
    for (int idx = tid; idx < 1536; idx += NTHR) WIHs[idx] = W_ih[idx];
    for (int idx = tid; idx < 768;  idx += NTHR) { BIHs[idx] = b_ih[idx]; BHHs[idx] = b_hh[idx]; }
    for (int idx = tid; idx < 512;  idx += NTHR) WOUTs[idx] = W_out[idx];
    if (tid < 2) BOUTs[tid] = b_out[tid];
    for (int idx = tid; idx < 128;  idx += NTHR) { GOALS[idx] = goals[row0 * 2 + idx]; POSs[idx] = 0.0f; }
    __syncthreads();

    // ---- hoisted per-lane gate constants (warp owns j-columns jj of each gate) ----
    const int jj = warp * 32 + lane;          // 0..255
    const float wir0 = WIHs[jj * 2],          wir1 = WIHs[jj * 2 + 1];
    const float wiz0 = WIHs[(jj + 256) * 2],  wiz1 = WIHs[(jj + 256) * 2 + 1];
    const float win0 = WIHs[(jj + 512) * 2],  win1 = WIHs[(jj + 512) * 2 + 1];
    const float bir  = BIHs[jj], biz = BIHs[jj + 256], bin = BIHs[jj + 512];
    const float bhr  = BHHs[jj], bhz = BHHs[jj + 256], bhn = BHHs[jj + 512];
    const float bo0  = BOUTs[0], bo1 = BOUTs[1];

    // ---- T-step GRU recurrence: j-sliced GEMM, 16-row passes ----
    const unsigned long long* WP =
        reinterpret_cast<const unsigned long long*>(g_Wp);
    float* hc  = HA;
    float* hnx = HB;
    for (int t = 0; t < T_; t++) {
        // [A] gemm + gates: warp computes its 32 j-columns for all 64 rows
        for (int pass = 0; pass < NPASS; pass++) {
            const int rbase = pass * RT;
            unsigned long long ar2[RT], az2[RT], an2[RT];
            #pragma unroll
            for (int rr = 0; rr < RT; rr++) { ar2[rr] = 0ull; az2[rr] = 0ull; an2[rr] = 0ull; }

            const unsigned long long* wp = WP + jj;
            #pragma unroll 2
            for (int kk = 0; kk < 64; kk++) {
                unsigned long long wr0 = wp[0];
                unsigned long long wz0 = wp[256];
                unsigned long long wn0 = wp[512];
                unsigned long long wr1 = wp[768];
                unsigned long long wz1 = wp[1024];
                unsigned long long wn1 = wp[1280];
                wp += 1536;
                const float* hrow = hc + rbase * 256 + kk * 4;
                #pragma unroll
                for (int rr = 0; rr < RT; rr++) {
                    ulonglong2 hv = *reinterpret_cast<const ulonglong2*>(
                        hrow + rr * 256);                  // broadcast LDS.128
                    ffma2(ar2[rr], hv.x, wr0); ffma2(ar2[rr], hv.y, wr1);
                    ffma2(az2[rr], hv.x, wz0); ffma2(az2[rr], hv.y, wz1);
                    ffma2(an2[rr], hv.x, wn0); ffma2(an2[rr], hv.y, wn1);
                }
            }

            // gate math for this 16-row tile, this lane's j column
            #pragma unroll
            for (int rr = 0; rr < RT; rr++) {
                const int r = rbase + rr;
                float p0 = POSs[r * 2 + 0];
                float p1 = POSs[r * 2 + 1];
                float ghr = fsum2(ar2[rr]) + bhr;
                float ghz = fsum2(az2[rr]) + bhz;
                float ghn = fsum2(an2[rr]) + bhn;
                float gir = fmaf(p0, wir0, fmaf(p1, wir1, bir));
                float giz = fmaf(p0, wiz0, fmaf(p1, wiz1, biz));
                float gin = fmaf(p0, win0, fmaf(p1, win1, bin));
                float rg  = sigm(gir + ghr);
                float zg  = sigm(giz + ghz);
                float ng  = tanhfast(fmaf(rg, ghn, gin));
                float hold = hc[r * 256 + jj];
                float hnew = fmaf(zg, hold - ng, ng);   // (1-z)n + z h
                hnx[r * 256 + jj] = hnew;
            }
        }
        __syncthreads();   // hnx complete (all j columns, all rows)

        // [B] delta pass: warp owns rows 8w..8w+7, reduce over all 256 j
        {
            const int r0d = warp * 8;
            float dAcc[16];
            #pragma unroll
            for (int i = 0; i < 16; i++) dAcc[i] = 0.0f;
            for (int jt = 0; jt < 8; jt++) {
                int j = jt * 32 + lane;
                float wo0 = WOUTs[j], wo1 = WOUTs[256 + j];
                #pragma unroll
                for (int rr = 0; rr < 8; rr++) {
                    float hn = hnx[(r0d + rr) * 256 + j];
                    dAcc[rr * 2 + 0] = fmaf(hn, wo0, dAcc[rr * 2 + 0]);
                    dAcc[rr * 2 + 1] = fmaf(hn, wo1, dAcc[rr * 2 + 1]);
                }
            }
            #pragma unroll
            for (int i = 0; i < 16; i++) {
                #pragma unroll
                for (int off = 16; off; off >>= 1)
                    dAcc[i] += __shfl_xor_sync(0xffffffffu, dAcc[i], off);
            }
            if (lane < 16) {
                int rr = lane >> 1, d = lane & 1;
                float bo = d ? bo1 : bo0;
                float np = POSs[(r0d + rr) * 2 + d] + dAcc[lane] + bo;
                POSs[(r0d + rr) * 2 + d] = np;
                PRED[(r0d + rr) * 60 + t * 2 + d] = np;
            }
        }
        __syncthreads();   // POSs + hnx stable before next step
        float* tmp = hc; hc = hnx; hnx = tmp;
    }

    // ---- goal-anchored correction + output write (B,K,T,2) ----
    const float inv = 1.0f / 30.0f;
    for (int idx = tid; idx < ROWS * 60; idx += NTHR) {
        int r = idx / 60, rem = idx % 60;
        int tt = rem >> 1, d = rem & 1;
        float last = PRED[r * 60 + 58 + d];
        float corr = GOALS[r * 2 + d] - last;
        out[(row0 + r) * 60 + rem] = PRED[idx] + corr * (float)(tt + 1) * inv;
    }
}

extern "C" void kernel_launch(void* const* d_in, const int* in_sizes, int n_in,
                              void* d_out, int out_size) {
    const float* context = (const float*)d_in[0];
    const float* goals   = (const float*)d_in[1];
    const float* intent  = (const float*)d_in[2];
    const float* W_h0    = (const float*)d_in[3];
    const float* b_h0    = (const float*)d_in[4];
    const float* W_ih    = (const float*)d_in[5];
    const float* W_hh    = (const float*)d_in[6];
    const float* b_ih    = (const float*)d_in[7];
    const float* b_hh    = (const float*)d_in[8];
    const float* W_out   = (const float*)d_in[9];
    const float* b_out   = (const float*)d_in[10];
    float* out = (float*)d_out;

    int prep_n = 146 * 256 + 128 * 768;
    prep_kernel<<<(prep_n + 255) / 256, 256>>>(W_h0, W_hh);

    size_t smem = SM_FLOATS * sizeof(float);
    cudaFuncSetAttribute(traj_kernel,
                         cudaFuncAttributeMaxDynamicSharedMemorySize, (int)smem);
    traj_kernel<<<NCTA, NTHR, smem>>>(context, goals, intent, b_h0,
                                      W_ih, b_ih, b_hh, W_out, b_out, out);
}